// round 11
// baseline (speedup 1.0000x reference)
#include <cuda_runtime.h>
#include <math.h>

// Problem constants (reference: B=16, H=W=96, TAU=0.5)
#define NB    16
#define HW    96
#define NPIX  (HW * HW)        // 9216
#define NCW   3                // 96-bit column-mask words
#define RPB   8                // rows per block
#define NCHUNK (HW / RPB)      // 12
#define G_INF 20000            // > max real D^2 (18050)
#define MAIN_BLOCKS (NB * 2 * NCHUNK)  // 384

// Persistent scratch (no allocations). All zero at module load; the last
// block resets everything to zero at the end of every execution, so each
// run (correctness call or graph replay) sees identical initial state.
__device__ __align__(16) unsigned g_cm[2][NB][HW * NCW]; // column bitmasks
__device__ int      g_cnt[2][NB];      // set cardinalities
__device__ int      g_r[NB][2];        // directed results (squared)
__device__ volatile unsigned g_ready[NB];  // mask-publish counters (target 6)
__device__ unsigned g_done;            // completion counter

// ---------------------------------------------------------------------------
// One fused kernel. grid = 16 img * 2 dir * 12 chunks = 384, block = 384.
// Blocks with chunk < 3 additionally build the column bitmasks for
// (set = dir, word-row = chunk) and publish via fence + g_ready counter.
// Single wave guaranteed: launch_bounds(384,4) -> >=4 blocks/SM -> 592 > 384,
// so producer/consumer spin cannot deadlock.
// ---------------------------------------------------------------------------
__global__ void __launch_bounds__(384, 4) hd_fused(
        const float* __restrict__ pred,
        const float* __restrict__ targ,
        float* __restrict__ out) {
    int blk = blockIdx.x;
    int chunk = blk % NCHUNK, dir = (blk / NCHUNK) & 1, img = blk / (2 * NCHUNK);
    int sset = dir, tset = dir ^ 1;
    int y0 = chunk * RPB;
    int tid = threadIdx.x, lane = tid & 31, wid = tid >> 5;

    __shared__ __align__(16) unsigned rm[32 * 3];    // producer staging
    __shared__ int      cnt_sh;
    __shared__ __align__(16) unsigned tcm[HW * NCW]; // target column masks
    __shared__ __align__(16) unsigned scm[HW * NCW]; // source column masks
    __shared__ __align__(16) int      Gs[RPB * HW];  // column EDT, 8 rows
    __shared__ int      smax;            // block running max

    // ---- producer: build masks for (set=dir, w=chunk), rows [32w,32w+32)
    if (chunk < 3) {
        int set = dir, w = chunk;
        const float* src = (set ? targ : pred) + img * NPIX + (w * 32) * HW;
        if (tid == 0) cnt_sh = 0;
        __syncthreads();
        if (tid < 256) {                 // 8 full warps
            int local = 0;
#pragma unroll
            for (int k = 0; k < 4; k++) {
                int r = wid * 4 + k;
#pragma unroll
                for (int c = 0; c < 3; c++) {
                    bool v = src[r * HW + c * 32 + lane] >= 0.5f;
                    unsigned bal = __ballot_sync(0xffffffffu, v);
                    if (lane == 0) { rm[r * 3 + c] = bal; local += __popc(bal); }
                }
            }
            if (lane == 0) atomicAdd(&cnt_sh, local);
        }
        __syncthreads();
        if (tid < 256) {                 // transpose -> column-major words
#pragma unroll
            for (int k = 0; k < 12; k++) {
                int x = wid * 12 + k;
                unsigned bit = (rm[lane * 3 + (x >> 5)] >> (x & 31)) & 1u;
                unsigned cw = __ballot_sync(0xffffffffu, bit);
                if (lane == 0) g_cm[set][img][x * 3 + w] = cw;
            }
        }
        __syncthreads();
        if (tid == 0) {
            atomicAdd(&g_cnt[set][img], cnt_sh);
            __threadfence();             // release: masks+count before counter
            atomicAdd((unsigned*)&g_ready[img], 1u);
        }
    }

    // ---- acquire: wait until all 6 mask units of this image are published
    if (tid == 0) {
        while (g_ready[img] != 6u) __nanosleep(32);
        __threadfence();                 // acquire (fresh L1)
        smax = g_r[img][dir];            // monotone: cross-block prune seed
    }
    __syncthreads();

    // wide coalesced mask loads into shared (72 uint4 each)
    if (tid < 72)
        ((uint4*)tcm)[tid] = ((const uint4*)g_cm[tset][img])[tid];
    else if (tid < 144)
        ((uint4*)scm)[tid - 72] = ((const uint4*)g_cm[sset][img])[tid - 72];
    __syncthreads();

    // ---- column EDT for the block's 8 rows: 2 pixels/thread via bit scans
#pragma unroll
    for (int k = 0; k < 2; k++) {
        int p = tid + k * 384;
        int r = p / HW, x = p - r * HW;
        int y = y0 + r;
        unsigned c0 = tcm[x * 3], c1 = tcm[x * 3 + 1], c2 = tcm[x * 3 + 2];
        int w = y >> 5, b = y & 31;
        unsigned lowm = (2u << b) - 1u;
        unsigned him  = 0xffffffffu << b;

        unsigned m0 = (w == 0) ? (c0 & him) : 0u;
        unsigned m1 = (w < 1) ? c1 : ((w == 1) ? (c1 & him) : 0u);
        unsigned m2 = (w < 2) ? c2 : (c2 & him);
        int i2 = m2 ? 64 + __ffs(m2) - 1 : (1 << 14);
        int i1 = m1 ? 32 + __ffs(m1) - 1 : i2;
        int lo = m0 ? __ffs(m0) - 1 : i1;
        int dd = lo - y;

        unsigned h0 = (w == 0) ? (c0 & lowm) : c0;
        unsigned h1 = (w < 1) ? 0u : ((w == 1) ? (c1 & lowm) : c1);
        unsigned h2 = (w < 2) ? 0u : (c2 & lowm);
        int j0 = h0 ? 31 - __clz(h0) : -(1 << 14);
        int j1 = h1 ? 63 - __clz(h1) : j0;
        int hi = h2 ? 95 - __clz(h2) : j1;
        int du = y - hi;

        int d = min(dd, du);
        Gs[r * HW + x] = min(d * d, G_INF);
    }
    __syncthreads();

    int cntT = g_cnt[tset][img];

    if (cntT > 0) {
        // pruned windowed scan over source-masked pixels.
        // Exact: (a) window stop at k^2 >= best is lossless (G >= 0);
        //        (b) skipping when G[x] <= smax is lossless (D^2 <= G[x]).
#pragma unroll
        for (int k = 0; k < 2; k++) {
            int p = tid + k * 384;
            int r = p / HW, x = p - r * HW;
            int y = y0 + r;
            if (!((scm[x * 3 + (y >> 5)] >> (y & 31)) & 1)) continue;

            const int* Gr = &Gs[r * HW];
            int best = Gr[x];
            int s = smax;                 // stale read: pruning only
            if (best <= s) continue;
            for (int kk = 1; kk < HW && kk * kk < best; kk++) {
                int q = kk * kk;
                int xl = x - kk, xr = x + kk;
                if (xl >= 0) best = min(best, Gr[xl] + q);
                if (xr < HW) best = min(best, Gr[xr] + q);
                if (best <= s) break;
            }
            if (best > s) atomicMax(&smax, best);
        }
    } else {
        // target empty: directed result = diameter of source set
        // (never taken for these inputs; kept for faithfulness)
        int lmax = 0;
        for (int p = tid; p < RPB * HW; p += 384) {
            int y = y0 + p / HW, x = p % HW;
            if (!((scm[x * 3 + (y >> 5)] >> (y & 31)) & 1)) continue;
            for (int q = 0; q < NPIX; q++) {
                int qy = q / HW, qx = q - qy * HW;
                if ((scm[qx * 3 + (qy >> 5)] >> (qy & 31)) & 1) {
                    int dy = y - qy, dx = x - qx;
                    lmax = max(lmax, dy * dy + dx * dx);
                }
            }
        }
        if (lmax > 0) atomicMax(&smax, lmax);
    }

    __syncthreads();
    if (tid == 0) {
        atomicMax(&g_r[img][dir], smax);
        __threadfence();
        unsigned t = atomicAdd(&g_done, 1u);
        if (t == MAIN_BLOCKS - 1) {
            __threadfence();
            // read-and-zero via atomicExch (L2-fresh) + compute output
            float sum = 0.f;
            for (int i = 0; i < NB; i++) {
                int a = atomicExch(&g_r[i][0], 0);
                int b = atomicExch(&g_r[i][1], 0);
                sum += sqrtf((float)max(a, b));
            }
            out[0] = sum * (1.0f / NB);
            // reset remaining state for the next execution
            for (int i = 0; i < NB; i++) {
                g_ready[i] = 0;
                g_cnt[0][i] = 0;
                g_cnt[1][i] = 0;
            }
            __threadfence();
            g_done = 0;
        }
    }
}

extern "C" void kernel_launch(void* const* d_in, const int* in_sizes, int n_in,
                              void* d_out, int out_size) {
    const float* pred = (const float*)d_in[0];
    const float* targ = (const float*)d_in[1];

    hd_fused<<<MAIN_BLOCKS, 384>>>(pred, targ, (float*)d_out);
}